// round 1
// baseline (speedup 1.0000x reference)
#include <cuda_runtime.h>

#define HC 16
#define NFREQ 9
#define PQ (2048 * 2048)   /* 4,194,304 */
#define PF (2048 * 4096)   /* 8,388,608 */

// h_q in [0..15], h_ffn in [16..31]
__device__ float g_h[32];

// ---------------------------------------------------------------------------
// Prologue: gather s from hypercube, 16-pt rfft -> complex filter -> irfft ->
// Haar. Tiny scalar work; single thread.
// irfft semantics (pocketfft C2R): imaginary parts of DC and Nyquist bins do
// not contribute to the real output:
//   f[n] = (1/16)[ R0 + (-1)^n R8 + 2*sum_{k=1..7}( Rk cos(2pi k n/16)
//                                                 - Ik sin(2pi k n/16) ) ]
// ---------------------------------------------------------------------------
__global__ void prologue_kernel(const float* __restrict__ ctx,
                                const float* __restrict__ hyper,
                                const float* __restrict__ fw_q,
                                const float* __restrict__ ps_q,
                                const float* __restrict__ fw_f,
                                const float* __restrict__ ps_f) {
    if (threadIdx.x != 0 || blockIdx.x != 0) return;

    int i0 = (int)(ctx[0] * 15.0f);
    int i1 = (int)(ctx[1] * 15.0f);
    int i2 = (int)(ctx[2] * 15.0f);
    const float* s = hyper + (((size_t)i0 * HC + i1) * HC + i2) * HC;

    float sv[16];
#pragma unroll
    for (int n = 0; n < 16; n++) sv[n] = s[n];

    const float PI = 3.14159265358979323846f;

    // rfft(s): S[k] = sum_n s[n] * exp(-2*pi*i*k*n/16), k = 0..8
    float Sr[NFREQ], Si[NFREQ];
#pragma unroll
    for (int k = 0; k < NFREQ; k++) {
        float re = 0.0f, im = 0.0f;
#pragma unroll
        for (int n = 0; n < 16; n++) {
            float ang = (2.0f * PI / 16.0f) * (float)(k * n);
            float c, sn;
            sincosf(ang, &sn, &c);
            re += sv[n] * c;
            im -= sv[n] * sn;
        }
        Sr[k] = re;
        Si[k] = im;
    }

    const float inv_sqrt2 = 0.7071067811865476f;

#pragma unroll
    for (int head = 0; head < 2; head++) {
        const float* fw = head ? fw_f : fw_q;
        const float* ps = head ? ps_f : ps_q;

        float R[NFREQ], I[NFREQ];
#pragma unroll
        for (int k = 0; k < NFREQ; k++) {
            float a = fw[k], b = ps[k];
            R[k] = Sr[k] * a - Si[k] * b;
            I[k] = Sr[k] * b + Si[k] * a;
        }

        float f[16];
#pragma unroll
        for (int n = 0; n < 16; n++) {
            float acc = R[0] + ((n & 1) ? -R[8] : R[8]);
#pragma unroll
            for (int k = 1; k <= 7; k++) {
                float ang = (2.0f * PI / 16.0f) * (float)(k * n);
                float c, sn;
                sincosf(ang, &sn, &c);
                acc += 2.0f * (R[k] * c - I[k] * sn);
            }
            f[n] = acc * (1.0f / 16.0f);
        }

        // Haar: h[j] = (e+o)/sqrt2, h[8+j] = (e-o)/sqrt2
#pragma unroll
        for (int j = 0; j < 8; j++) {
            g_h[head * 16 + j]     = (f[2 * j] + f[2 * j + 1]) * inv_sqrt2;
            g_h[head * 16 + 8 + j] = (f[2 * j] - f[2 * j + 1]) * inv_sqrt2;
        }
    }
}

// ---------------------------------------------------------------------------
// Main: out[r] = W[r, 0:16] . h + b[r] for 12M rows.
// Each thread handles 4 contiguous rows: 16x LDG.128 of W (256B contiguous
// per thread), float4 b load, float4 store. Pure HBM stream.
// Grid: blocks [0, PQ/1024) -> Q head; blocks [PQ/1024, +PF/1024) -> FFN head.
// ---------------------------------------------------------------------------
#define QBLOCKS (PQ / 1024)  /* 4096  */
#define FBLOCKS (PF / 1024)  /* 8192  */

__global__ void __launch_bounds__(256)
gemv_kernel(const float4* __restrict__ Wq, const float4* __restrict__ bq,
            const float4* __restrict__ Wf, const float4* __restrict__ bf,
            float4* __restrict__ out) {
    __shared__ float hs[16];

    const bool isQ = (blockIdx.x < QBLOCKS);
    if (threadIdx.x < 16) hs[threadIdx.x] = g_h[(isQ ? 0 : 16) + threadIdx.x];
    __syncthreads();

    float h[16];
#pragma unroll
    for (int i = 0; i < 16; i++) h[i] = hs[i];

    const float4* __restrict__ W;
    const float4* __restrict__ bv;
    float4* __restrict__ o;
    size_t t;
    if (isQ) {
        t  = (size_t)blockIdx.x * 256 + threadIdx.x;
        W  = Wq;  bv = bq;  o = out;
    } else {
        t  = (size_t)(blockIdx.x - QBLOCKS) * 256 + threadIdx.x;
        W  = Wf;  bv = bf;  o = out + (PQ / 4);
    }

    // thread t covers rows 4t .. 4t+3 ; W float4 index = row*4 + j
    const size_t base = t * 16;

    float4 res = bv[t];

    float4 w;
    // row 0 (res.x)
    w = W[base + 0];  res.x += w.x * h[0]  + w.y * h[1]  + w.z * h[2]  + w.w * h[3];
    w = W[base + 1];  res.x += w.x * h[4]  + w.y * h[5]  + w.z * h[6]  + w.w * h[7];
    w = W[base + 2];  res.x += w.x * h[8]  + w.y * h[9]  + w.z * h[10] + w.w * h[11];
    w = W[base + 3];  res.x += w.x * h[12] + w.y * h[13] + w.z * h[14] + w.w * h[15];
    // row 1 (res.y)
    w = W[base + 4];  res.y += w.x * h[0]  + w.y * h[1]  + w.z * h[2]  + w.w * h[3];
    w = W[base + 5];  res.y += w.x * h[4]  + w.y * h[5]  + w.z * h[6]  + w.w * h[7];
    w = W[base + 6];  res.y += w.x * h[8]  + w.y * h[9]  + w.z * h[10] + w.w * h[11];
    w = W[base + 7];  res.y += w.x * h[12] + w.y * h[13] + w.z * h[14] + w.w * h[15];
    // row 2 (res.z)
    w = W[base + 8];  res.z += w.x * h[0]  + w.y * h[1]  + w.z * h[2]  + w.w * h[3];
    w = W[base + 9];  res.z += w.x * h[4]  + w.y * h[5]  + w.z * h[6]  + w.w * h[7];
    w = W[base + 10]; res.z += w.x * h[8]  + w.y * h[9]  + w.z * h[10] + w.w * h[11];
    w = W[base + 11]; res.z += w.x * h[12] + w.y * h[13] + w.z * h[14] + w.w * h[15];
    // row 3 (res.w)
    w = W[base + 12]; res.w += w.x * h[0]  + w.y * h[1]  + w.z * h[2]  + w.w * h[3];
    w = W[base + 13]; res.w += w.x * h[4]  + w.y * h[5]  + w.z * h[6]  + w.w * h[7];
    w = W[base + 14]; res.w += w.x * h[8]  + w.y * h[9]  + w.z * h[10] + w.w * h[11];
    w = W[base + 15]; res.w += w.x * h[12] + w.y * h[13] + w.z * h[14] + w.w * h[15];

    o[t] = res;
}

// ---------------------------------------------------------------------------
// Launch
// Inputs (metadata order): context(3), hypercube(65536), fw_q(9), ps_q(9),
// W_q(PQ*16), b_q(PQ), fw_ffn(9), ps_ffn(9), W_ffn(PF*16), b_ffn(PF)
// Output: float32, out_q (PQ) followed by out_ffn (PF)
// ---------------------------------------------------------------------------
extern "C" void kernel_launch(void* const* d_in, const int* in_sizes, int n_in,
                              void* d_out, int out_size) {
    const float* ctx    = (const float*)d_in[0];
    const float* hyper  = (const float*)d_in[1];
    const float* fw_q   = (const float*)d_in[2];
    const float* ps_q   = (const float*)d_in[3];
    const float* W_q    = (const float*)d_in[4];
    const float* b_q    = (const float*)d_in[5];
    const float* fw_ffn = (const float*)d_in[6];
    const float* ps_ffn = (const float*)d_in[7];
    const float* W_ffn  = (const float*)d_in[8];
    const float* b_ffn  = (const float*)d_in[9];

    prologue_kernel<<<1, 32>>>(ctx, hyper, fw_q, ps_q, fw_ffn, ps_ffn);

    gemv_kernel<<<QBLOCKS + FBLOCKS, 256>>>(
        (const float4*)W_q, (const float4*)b_q,
        (const float4*)W_ffn, (const float4*)b_ffn,
        (float4*)d_out);
}

// round 2
// speedup vs baseline: 1.3742x; 1.3742x over previous
#include <cuda_runtime.h>

#define HC 16
#define NFREQ 9
#define PQ (2048 * 2048)   /* 4,194,304 rows  */
#define PF (2048 * 4096)   /* 8,388,608 rows  */

// h_q in [0..15], h_ffn in [16..31]
__device__ float g_h[32];

// ---------------------------------------------------------------------------
// Prologue: gather s from hypercube, 16-pt rfft -> complex filter -> irfft ->
// Haar. Tiny scalar work; single thread.
// ---------------------------------------------------------------------------
__global__ void prologue_kernel(const float* __restrict__ ctx,
                                const float* __restrict__ hyper,
                                const float* __restrict__ fw_q,
                                const float* __restrict__ ps_q,
                                const float* __restrict__ fw_f,
                                const float* __restrict__ ps_f) {
    if (threadIdx.x != 0 || blockIdx.x != 0) return;

    int i0 = (int)(ctx[0] * 15.0f);
    int i1 = (int)(ctx[1] * 15.0f);
    int i2 = (int)(ctx[2] * 15.0f);
    const float* s = hyper + (((size_t)i0 * HC + i1) * HC + i2) * HC;

    float sv[16];
#pragma unroll
    for (int n = 0; n < 16; n++) sv[n] = s[n];

    const float PI = 3.14159265358979323846f;

    // rfft(s): S[k] = sum_n s[n] * exp(-2*pi*i*k*n/16), k = 0..8
    float Sr[NFREQ], Si[NFREQ];
#pragma unroll
    for (int k = 0; k < NFREQ; k++) {
        float re = 0.0f, im = 0.0f;
#pragma unroll
        for (int n = 0; n < 16; n++) {
            float ang = (2.0f * PI / 16.0f) * (float)(k * n);
            float c, sn;
            sincosf(ang, &sn, &c);
            re += sv[n] * c;
            im -= sv[n] * sn;
        }
        Sr[k] = re;
        Si[k] = im;
    }

    const float inv_sqrt2 = 0.7071067811865476f;

#pragma unroll
    for (int head = 0; head < 2; head++) {
        const float* fw = head ? fw_f : fw_q;
        const float* ps = head ? ps_f : ps_q;

        float R[NFREQ], I[NFREQ];
#pragma unroll
        for (int k = 0; k < NFREQ; k++) {
            float a = fw[k], b = ps[k];
            R[k] = Sr[k] * a - Si[k] * b;
            I[k] = Sr[k] * b + Si[k] * a;
        }

        // irfft (pocketfft C2R): imag of DC/Nyquist ignored
        float f[16];
#pragma unroll
        for (int n = 0; n < 16; n++) {
            float acc = R[0] + ((n & 1) ? -R[8] : R[8]);
#pragma unroll
            for (int k = 1; k <= 7; k++) {
                float ang = (2.0f * PI / 16.0f) * (float)(k * n);
                float c, sn;
                sincosf(ang, &sn, &c);
                acc += 2.0f * (R[k] * c - I[k] * sn);
            }
            f[n] = acc * (1.0f / 16.0f);
        }

        // Haar
#pragma unroll
        for (int j = 0; j < 8; j++) {
            g_h[head * 16 + j]     = (f[2 * j] + f[2 * j + 1]) * inv_sqrt2;
            g_h[head * 16 + 8 + j] = (f[2 * j] - f[2 * j + 1]) * inv_sqrt2;
        }
    }
}

// ---------------------------------------------------------------------------
// Main GEMV, fully coalesced.
// Unit = one float4 of W (a quarter-row). Thread tid owns quarter (tid&3)
// forever, so it holds only h[4q..4q+3]. Per thread: U=8 coalesced LDG.128
// (lanes load CONSECUTIVE float4s -> 4 wavefronts/instr, the L1 floor),
// then per unit a 4-FFMA partial dot + shfl.bfly(1) + shfl.bfly(2) reduction
// across the 4 lanes sharing a row. Lane q==0 adds b[row] and stores.
// Block covers 2048 float4s = 512 rows = 32KB of W.
// ---------------------------------------------------------------------------
#define UNROLL 8
#define TPB 256
#define UNITS_PER_BLOCK (UNROLL * TPB)          /* 2048 */
#define QB ((PQ * 4) / UNITS_PER_BLOCK)         /* 8192 blocks  */
#define FB ((PF * 4) / UNITS_PER_BLOCK)         /* 16384 blocks */

__global__ void __launch_bounds__(TPB)
gemv_kernel(const float4* __restrict__ Wq, const float* __restrict__ bq,
            const float4* __restrict__ Wf, const float* __restrict__ bf,
            float* __restrict__ out) {
    const int tid = threadIdx.x;
    const bool isQ = (blockIdx.x < QB);

    const float4* __restrict__ W;
    const float*  __restrict__ b;
    float* __restrict__ o;
    size_t ubase;  // first float4 unit of this block
    if (isQ) {
        W = Wq; b = bq; o = out;
        ubase = (size_t)blockIdx.x * UNITS_PER_BLOCK;
    } else {
        W = Wf; b = bf; o = out + PQ;
        ubase = (size_t)(blockIdx.x - QB) * UNITS_PER_BLOCK;
    }

    const int q = tid & 3;   // which quarter of h this thread always handles
    float h0, h1, h2, h3;
    {
        const float* hh = g_h + (isQ ? 0 : 16) + 4 * q;
        h0 = hh[0]; h1 = hh[1]; h2 = hh[2]; h3 = hh[3];
    }

    // Front-batched, fully coalesced loads (MLP = 8)
    float4 w[UNROLL];
#pragma unroll
    for (int j = 0; j < UNROLL; j++)
        w[j] = W[ubase + (size_t)j * TPB + tid];

#pragma unroll
    for (int j = 0; j < UNROLL; j++) {
        float p = w[j].x * h0 + w[j].y * h1 + w[j].z * h2 + w[j].w * h3;
        p += __shfl_xor_sync(0xffffffffu, p, 1);
        p += __shfl_xor_sync(0xffffffffu, p, 2);
        if (q == 0) {
            size_t row = (ubase + (size_t)j * TPB + tid) >> 2;
            o[row] = p + b[row];
        }
    }
}

// ---------------------------------------------------------------------------
// Launch.
// Inputs (metadata order): context(3), hypercube(65536), fw_q(9), ps_q(9),
// W_q(PQ*16), b_q(PQ), fw_ffn(9), ps_ffn(9), W_ffn(PF*16), b_ffn(PF)
// Output: float32, out_q (PQ) followed by out_ffn (PF)
// ---------------------------------------------------------------------------
extern "C" void kernel_launch(void* const* d_in, const int* in_sizes, int n_in,
                              void* d_out, int out_size) {
    const float* ctx    = (const float*)d_in[0];
    const float* hyper  = (const float*)d_in[1];
    const float* fw_q   = (const float*)d_in[2];
    const float* ps_q   = (const float*)d_in[3];
    const float* W_q    = (const float*)d_in[4];
    const float* b_q    = (const float*)d_in[5];
    const float* fw_ffn = (const float*)d_in[6];
    const float* ps_ffn = (const float*)d_in[7];
    const float* W_ffn  = (const float*)d_in[8];
    const float* b_ffn  = (const float*)d_in[9];

    prologue_kernel<<<1, 32>>>(ctx, hyper, fw_q, ps_q, fw_ffn, ps_ffn);

    gemv_kernel<<<QB + FB, TPB>>>(
        (const float4*)W_q, b_q,
        (const float4*)W_ffn, b_ffn,
        (float*)d_out);
}